// round 5
// baseline (speedup 1.0000x reference)
#include <cuda_runtime.h>
#include <cuda_fp16.h>

#define N_NODES 100000
#define N_EDGES 1200000
#define D 64
#define OUT_COLS 384

// Scratch (fp16 gather tables)
__device__ __half2 g_hn[(size_t)N_NODES * 32];   // LN(feature): 64 halves/node (128 B)
__device__ __half2 g_h [(size_t)N_NODES * 96];   // layer-1 h: 3 windows x 64 halves (384 B)
__device__ int g_deg   [N_NODES];
__device__ int g_beg   [N_NODES];
__device__ int g_cursor[N_NODES];
__device__ int g_csr   [N_EDGES];
__device__ int g_total;

// ---------- warp LayerNorm over 64 floats (float2 per lane) ----------
__device__ __forceinline__ float2 warp_ln(float2 v) {
    float s  = v.x + v.y;
    float ss = v.x * v.x + v.y * v.y;
    #pragma unroll
    for (int o = 16; o; o >>= 1) {
        s  += __shfl_xor_sync(0xFFFFFFFFu, s,  o);
        ss += __shfl_xor_sync(0xFFFFFFFFu, ss, o);
    }
    float mu  = s * (1.0f / D);
    float var = ss * (1.0f / D) - mu * mu;
    float r   = rsqrtf(var + 1e-5f);
    return make_float2((v.x - mu) * r, (v.y - mu) * r);
}

__device__ __forceinline__ void unpack8(int4 v, float* f) {
    __half2* hv = reinterpret_cast<__half2*>(&v);
    #pragma unroll
    for (int i = 0; i < 4; i++) {
        float2 t = __half22float2(hv[i]);
        f[2 * i] = t.x; f[2 * i + 1] = t.y;
    }
}
__device__ __forceinline__ int4 pack8(const float* f) {
    int4 v;
    __half2* hv = reinterpret_cast<__half2*>(&v);
    #pragma unroll
    for (int i = 0; i < 4; i++)
        hv[i] = __floats2half2_rn(f[2 * i], f[2 * i + 1]);
    return v;
}

// 8-lane-group LN over 64 features (8 per lane), then ReLU, in place.
__device__ __forceinline__ void group_ln_relu(float* a) {
    float s = 0.f, ss = 0.f;
    #pragma unroll
    for (int i = 0; i < 8; i++) { s += a[i]; ss += a[i] * a[i]; }
    #pragma unroll
    for (int o = 1; o <= 4; o <<= 1) {
        s  += __shfl_xor_sync(0xFFFFFFFFu, s,  o);
        ss += __shfl_xor_sync(0xFFFFFFFFu, ss, o);
    }
    float mu  = s * (1.0f / D);
    float var = ss * (1.0f / D) - mu * mu;
    float r   = rsqrtf(var + 1e-5f);
    #pragma unroll
    for (int i = 0; i < 8; i++) a[i] = fmaxf((a[i] - mu) * r, 0.f);
}

// ---------- init: hn = LN(feature) -> fp16; layer-0 output; zero deg/total ----------
__global__ __launch_bounds__(256) void init_kernel(
    const float* __restrict__ feat, const int* __restrict__ age,
    float* __restrict__ out)
{
    int n    = (blockIdx.x * blockDim.x + threadIdx.x) >> 5;
    int lane = threadIdx.x & 31;
    if (blockIdx.x == 0 && threadIdx.x == 0) g_total = 0;
    if (n >= N_NODES) return;
    if (lane == 0) g_deg[n] = 0;

    float2 v  = reinterpret_cast<const float2*>(feat + (size_t)n * D)[lane];
    float2 hn = warp_ln(v);
    g_hn[(size_t)n * 32 + lane] = __float22half2_rn(hn);

    int a = age[n];
    float tf = 1.0f - 0.5f * ((a >= 1 ? 1.f : 0.f) + (a >= 2 ? 1.f : 0.f));
    float* ob = out + (size_t)n * OUT_COLS;
    reinterpret_cast<float2*>(ob)[lane]       = hn;
    reinterpret_cast<float2*>(ob + 192)[lane] = make_float2(hn.x * tf, hn.y * tf);
}

// ---------- CSR build: hist -> block-aggregated atomic alloc -> scatter ----------
__global__ __launch_bounds__(256) void hist_kernel(const int* __restrict__ dst) {
    int e = blockIdx.x * blockDim.x + threadIdx.x;
    if (e < N_EDGES) atomicAdd(&g_deg[dst[e]], 1);
}

__global__ __launch_bounds__(256) void alloc_kernel() {
    __shared__ int wsum[8];
    __shared__ int blockbase;
    int i    = blockIdx.x * 256 + threadIdx.x;
    int lane = threadIdx.x & 31;
    int wid  = threadIdx.x >> 5;

    int d = (i < N_NODES) ? g_deg[i] : 0;
    int incl = d;
    #pragma unroll
    for (int o = 1; o < 32; o <<= 1) {
        int t = __shfl_up_sync(0xFFFFFFFFu, incl, o);
        if (lane >= o) incl += t;
    }
    if (lane == 31) wsum[wid] = incl;
    __syncthreads();
    if (wid == 0) {
        int v = (lane < 8) ? wsum[lane] : 0;
        #pragma unroll
        for (int o = 1; o < 8; o <<= 1) {
            int t = __shfl_up_sync(0xFFFFFFFFu, v, o);
            if (lane >= o) v += t;
        }
        if (lane < 8) wsum[lane] = v;                 // inclusive warp prefixes
        if (lane == 7) blockbase = atomicAdd(&g_total, v);
    }
    __syncthreads();
    int excl = incl - d + (wid > 0 ? wsum[wid - 1] : 0);
    int base = blockbase + excl;
    if (i < N_NODES) { g_beg[i] = base; g_cursor[i] = base; }
}

__global__ __launch_bounds__(256) void scatter_kernel(
    const int* __restrict__ src, const int* __restrict__ dst)
{
    int e = blockIdx.x * blockDim.x + threadIdx.x;
    if (e >= N_EDGES) return;
    int pos = atomicAdd(&g_cursor[dst[e]], 1);
    g_csr[pos] = src[e];
}

// ---------- layer 1: vectorized gather (4 neighbors / warp-instruction) ----------
__global__ __launch_bounds__(256) void layer1_kernel(
    const int* __restrict__ age, float* __restrict__ out)
{
    int n    = (blockIdx.x * blockDim.x + threadIdx.x) >> 5;
    int lane = threadIdx.x & 31;
    if (n >= N_NODES) return;
    int k   = lane & 7;     // feature slice: halves [8k, 8k+8)
    int grp = lane >> 3;    // neighbor subgroup 0..3

    int beg = g_beg[n], deg = g_deg[n], end = beg + deg;
    float a0[8], a1[8], a2[8];
    #pragma unroll
    for (int i = 0; i < 8; i++) { a0[i] = 0.f; a1[i] = 0.f; a2[i] = 0.f; }

    for (int base = beg; base < end; base += 32) {
        int cnt = min(32, end - base);
        int idx = (lane < cnt) ? __ldg(g_csr + base + lane) : 0;
        int ag  = (lane < cnt) ? __ldg(age + idx) : 0;
        for (int j = 0; j < cnt; j += 4) {
            int myn = j + grp;                                 // <= 31 always
            int s   = __shfl_sync(0xFFFFFFFFu, idx, myn);
            int sa  = __shfl_sync(0xFFFFFFFFu, ag,  myn);
            int4 v  = __ldg(reinterpret_cast<const int4*>(g_hn + (size_t)s * 32) + k);
            float f[8];
            unpack8(v, f);
            if (myn < cnt) {
                #pragma unroll
                for (int i = 0; i < 8; i++) a0[i] += f[i];
                if (sa >= 1) {
                    #pragma unroll
                    for (int i = 0; i < 8; i++) a1[i] += f[i];
                }
                if (sa >= 2) {
                    #pragma unroll
                    for (int i = 0; i < 8; i++) a2[i] += f[i];
                }
            }
        }
    }

    // combine the 4 neighbor subgroups
    #pragma unroll
    for (int o = 8; o <= 16; o <<= 1) {
        #pragma unroll
        for (int i = 0; i < 8; i++) {
            a0[i] += __shfl_xor_sync(0xFFFFFFFFu, a0[i], o);
            a1[i] += __shfl_xor_sync(0xFFFFFFFFu, a1[i], o);
            a2[i] += __shfl_xor_sync(0xFFFFFFFFu, a2[i], o);
        }
    }

    group_ln_relu(a0);
    group_ln_relu(a1);
    group_ln_relu(a2);

    // store fp16 h table: lane l<24 stores int4 chunk l (window l/8, slice l%8)
    float o8[8];
    #pragma unroll
    for (int i = 0; i < 8; i++)
        o8[i] = (grp == 0) ? a0[i] : (grp == 1) ? a1[i] : a2[i];
    if (lane < 24)
        reinterpret_cast<int4*>(g_h + (size_t)n * 96)[lane] = pack8(o8);

    // outputs: lanes 0-7 write window0 layer1 block, lanes 8-15 temporal layer1
    float* ob = out + (size_t)n * OUT_COLS;
    if (lane < 8) {
        float4* p = reinterpret_cast<float4*>(ob + 64 + 8 * k);
        p[0] = make_float4(a0[0], a0[1], a0[2], a0[3]);
        p[1] = make_float4(a0[4], a0[5], a0[6], a0[7]);
    } else if (lane < 16) {
        float t[8];
        #pragma unroll
        for (int i = 0; i < 8; i++) t[i] = a0[i] - 0.5f * (a1[i] + a2[i]);
        float4* p = reinterpret_cast<float4*>(ob + 256 + 8 * k);
        p[0] = make_float4(t[0], t[1], t[2], t[3]);
        p[1] = make_float4(t[4], t[5], t[6], t[7]);
    }
}

// ---------- layer 2: vectorized gather (full 384B neighbor row / warp-instruction) ----------
__global__ __launch_bounds__(256) void layer2_kernel(float* __restrict__ out)
{
    int n    = (blockIdx.x * blockDim.x + threadIdx.x) >> 5;
    int lane = threadIdx.x & 31;
    if (n >= N_NODES) return;
    int k = lane & 7;       // feature slice; window = lane>>3 (lanes 24-31 idle)

    int beg = g_beg[n], deg = g_deg[n], end = beg + deg;
    float a[8];
    #pragma unroll
    for (int i = 0; i < 8; i++) a[i] = 0.f;

    for (int base = beg; base < end; base += 32) {
        int cnt = min(32, end - base);
        int idx = (lane < cnt) ? __ldg(g_csr + base + lane) : 0;
        for (int j = 0; j < cnt; j += 2) {
            int s0 = __shfl_sync(0xFFFFFFFFu, idx, j);
            int s1 = __shfl_sync(0xFFFFFFFFu, idx, (j + 1) & 31);
            bool has1 = (j + 1) < cnt;
            if (lane < 24) {
                int4 v0 = __ldg(reinterpret_cast<const int4*>(g_h + (size_t)s0 * 96) + lane);
                float f0[8];
                unpack8(v0, f0);
                if (has1) {
                    int4 v1 = __ldg(reinterpret_cast<const int4*>(g_h + (size_t)s1 * 96) + lane);
                    float f1[8];
                    unpack8(v1, f1);
                    #pragma unroll
                    for (int i = 0; i < 8; i++) a[i] += f0[i] + f1[i];
                } else {
                    #pragma unroll
                    for (int i = 0; i < 8; i++) a[i] += f0[i];
                }
            }
        }
    }

    group_ln_relu(a);   // per 8-lane group == per window

    float t[8];
    #pragma unroll
    for (int i = 0; i < 8; i++) {
        float v1 = __shfl_sync(0xFFFFFFFFu, a[i], k + 8);
        float v2 = __shfl_sync(0xFFFFFFFFu, a[i], k + 16);
        t[i] = a[i] - 0.5f * (v1 + v2);
    }
    if (lane < 8) {
        float* ob = out + (size_t)n * OUT_COLS;
        float4* p = reinterpret_cast<float4*>(ob + 128 + 8 * k);
        p[0] = make_float4(a[0], a[1], a[2], a[3]);
        p[1] = make_float4(a[4], a[5], a[6], a[7]);
        float4* q = reinterpret_cast<float4*>(ob + 320 + 8 * k);
        q[0] = make_float4(t[0], t[1], t[2], t[3]);
        q[1] = make_float4(t[4], t[5], t[6], t[7]);
    }
}

extern "C" void kernel_launch(void* const* d_in, const int* in_sizes, int n_in,
                              void* d_out, int out_size)
{
    const float* feat = (const float*)d_in[0];
    const int*   age  = (const int*)  d_in[1];
    const int*   src  = (const int*)  d_in[2];
    const int*   dst  = (const int*)  d_in[3];
    float* out = (float*)d_out;

    const int nodeWarpBlocks = (N_NODES * 32 + 255) / 256;  // 12500
    const int nodeBlocks     = (N_NODES + 255) / 256;       // 391
    const int edgeBlocks     = (N_EDGES + 255) / 256;       // 4688

    init_kernel<<<nodeWarpBlocks, 256>>>(feat, age, out);   // also zeros deg/total
    hist_kernel<<<edgeBlocks, 256>>>(dst);
    alloc_kernel<<<nodeBlocks, 256>>>();
    scatter_kernel<<<edgeBlocks, 256>>>(src, dst);
    layer1_kernel<<<nodeWarpBlocks, 256>>>(age, out);
    layer2_kernel<<<nodeWarpBlocks, 256>>>(out);
}

// round 6
// speedup vs baseline: 1.2424x; 1.2424x over previous
#include <cuda_runtime.h>
#include <cuda_fp16.h>

#define N_NODES 100000
#define N_EDGES 1200000
#define D 64
#define OUT_COLS 384

// Scratch (fp16 gather tables)
__device__ __half2 g_hn[(size_t)N_NODES * 32];   // LN(feature): 32 half2/node (128 B)
__device__ __half2 g_h [(size_t)N_NODES * 96];   // layer-1 h: [node][win3][32 half2] (384 B)
__device__ int g_deg   [N_NODES];
__device__ int g_beg   [N_NODES];
__device__ int g_cursor[N_NODES];
__device__ int g_csr   [N_EDGES];
__device__ int g_total;

// ---------- warp LayerNorm over 64 floats (float2 per lane), biased var, eps 1e-5 ----------
__device__ __forceinline__ float2 warp_ln(float2 v) {
    float s  = v.x + v.y;
    float ss = v.x * v.x + v.y * v.y;
    #pragma unroll
    for (int o = 16; o; o >>= 1) {
        s  += __shfl_xor_sync(0xFFFFFFFFu, s,  o);
        ss += __shfl_xor_sync(0xFFFFFFFFu, ss, o);
    }
    float mu  = s * (1.0f / D);
    float var = ss * (1.0f / D) - mu * mu;
    float r   = rsqrtf(var + 1e-5f);
    return make_float2((v.x - mu) * r, (v.y - mu) * r);
}
__device__ __forceinline__ float2 ln_relu(float2 v) {
    float2 n = warp_ln(v);
    return make_float2(fmaxf(n.x, 0.f), fmaxf(n.y, 0.f));
}
__device__ __forceinline__ void acc(float2& a, float2 v) { a.x += v.x; a.y += v.y; }

// ---------- init: hn = LN(feature) -> fp16; layer-0 output; zero deg/total ----------
__global__ __launch_bounds__(256) void init_kernel(
    const float* __restrict__ feat, const int* __restrict__ age,
    float* __restrict__ out)
{
    int n    = (blockIdx.x * blockDim.x + threadIdx.x) >> 5;
    int lane = threadIdx.x & 31;
    if (blockIdx.x == 0 && threadIdx.x == 0) g_total = 0;
    if (n >= N_NODES) return;
    if (lane == 0) g_deg[n] = 0;

    float2 v  = reinterpret_cast<const float2*>(feat + (size_t)n * D)[lane];
    float2 hn = warp_ln(v);
    g_hn[(size_t)n * 32 + lane] = __float22half2_rn(hn);

    int a = age[n];
    float tf = 1.0f - 0.5f * ((a >= 1 ? 1.f : 0.f) + (a >= 2 ? 1.f : 0.f));
    float* ob = out + (size_t)n * OUT_COLS;
    reinterpret_cast<float2*>(ob)[lane]       = hn;
    reinterpret_cast<float2*>(ob + 192)[lane] = make_float2(hn.x * tf, hn.y * tf);
}

// ---------- CSR build ----------
// hist: 4 edges/thread, coalesced batches, 4 atomics in flight
__global__ __launch_bounds__(256) void hist_kernel(const int* __restrict__ dst) {
    int base = blockIdx.x * 1024 + threadIdx.x;
    #pragma unroll
    for (int k = 0; k < 4; k++) {
        int e = base + k * 256;
        if (e < N_EDGES) atomicAdd(&g_deg[dst[e]], 1);
    }
}

__global__ __launch_bounds__(256) void alloc_kernel() {
    __shared__ int wsum[8];
    __shared__ int blockbase;
    int i    = blockIdx.x * 256 + threadIdx.x;
    int lane = threadIdx.x & 31;
    int wid  = threadIdx.x >> 5;

    int d = (i < N_NODES) ? g_deg[i] : 0;
    int incl = d;
    #pragma unroll
    for (int o = 1; o < 32; o <<= 1) {
        int t = __shfl_up_sync(0xFFFFFFFFu, incl, o);
        if (lane >= o) incl += t;
    }
    if (lane == 31) wsum[wid] = incl;
    __syncthreads();
    if (wid == 0) {
        int v = (lane < 8) ? wsum[lane] : 0;
        #pragma unroll
        for (int o = 1; o < 8; o <<= 1) {
            int t = __shfl_up_sync(0xFFFFFFFFu, v, o);
            if (lane >= o) v += t;
        }
        if (lane < 8) wsum[lane] = v;
        if (lane == 7) blockbase = atomicAdd(&g_total, v);
    }
    __syncthreads();
    int excl = incl - d + (wid > 0 ? wsum[wid - 1] : 0);
    int base = blockbase + excl;
    if (i < N_NODES) { g_beg[i] = base; g_cursor[i] = base; }
}

// scatter: 4 edges/thread, 4 independent atomics in flight
__global__ __launch_bounds__(256) void scatter_kernel(
    const int* __restrict__ src, const int* __restrict__ dst)
{
    int base = blockIdx.x * 1024 + threadIdx.x;
    int dv[4], sv[4], pos[4];
    #pragma unroll
    for (int k = 0; k < 4; k++) {
        int e = base + k * 256;
        if (e < N_EDGES) { dv[k] = __ldg(dst + e); sv[k] = __ldg(src + e); }
    }
    #pragma unroll
    for (int k = 0; k < 4; k++) {
        int e = base + k * 256;
        if (e < N_EDGES) pos[k] = atomicAdd(&g_cursor[dv[k]], 1);
    }
    #pragma unroll
    for (int k = 0; k < 4; k++) {
        int e = base + k * 256;
        if (e < N_EDGES) g_csr[pos[k]] = sv[k];
    }
}

// ---------- layer 1: gather hn(fp16) + src-age masks, 4-neighbor unroll ----------
__global__ __launch_bounds__(256) void layer1_kernel(
    const int* __restrict__ age, float* __restrict__ out)
{
    int n    = (blockIdx.x * blockDim.x + threadIdx.x) >> 5;
    int lane = threadIdx.x & 31;
    if (n >= N_NODES) return;

    int beg = g_beg[n], end = beg + g_deg[n];
    float2 a0 = make_float2(0.f, 0.f), a1 = a0, a2 = a0;

    for (int base = beg; base < end; base += 32) {
        int cnt = min(32, end - base);
        int idx = (lane < cnt) ? __ldg(g_csr + base + lane) : 0;
        int ag  = (lane < cnt) ? __ldg(age + idx) : 0;
        int j = 0;
        for (; j + 4 <= cnt; j += 4) {
            int s0 = __shfl_sync(0xFFFFFFFFu, idx, j);
            int s1 = __shfl_sync(0xFFFFFFFFu, idx, j + 1);
            int s2 = __shfl_sync(0xFFFFFFFFu, idx, j + 2);
            int s3 = __shfl_sync(0xFFFFFFFFu, idx, j + 3);
            int gA = __shfl_sync(0xFFFFFFFFu, ag, j);
            int gB = __shfl_sync(0xFFFFFFFFu, ag, j + 1);
            int gC = __shfl_sync(0xFFFFFFFFu, ag, j + 2);
            int gD = __shfl_sync(0xFFFFFFFFu, ag, j + 3);
            float2 v0 = __half22float2(g_hn[(size_t)s0 * 32 + lane]);
            float2 v1 = __half22float2(g_hn[(size_t)s1 * 32 + lane]);
            float2 v2 = __half22float2(g_hn[(size_t)s2 * 32 + lane]);
            float2 v3 = __half22float2(g_hn[(size_t)s3 * 32 + lane]);
            acc(a0, v0); if (gA >= 1) acc(a1, v0); if (gA >= 2) acc(a2, v0);
            acc(a0, v1); if (gB >= 1) acc(a1, v1); if (gB >= 2) acc(a2, v1);
            acc(a0, v2); if (gC >= 1) acc(a1, v2); if (gC >= 2) acc(a2, v2);
            acc(a0, v3); if (gD >= 1) acc(a1, v3); if (gD >= 2) acc(a2, v3);
        }
        for (; j < cnt; j++) {
            int s  = __shfl_sync(0xFFFFFFFFu, idx, j);
            int sa = __shfl_sync(0xFFFFFFFFu, ag,  j);
            float2 v = __half22float2(g_hn[(size_t)s * 32 + lane]);
            acc(a0, v); if (sa >= 1) acc(a1, v); if (sa >= 2) acc(a2, v);
        }
    }

    float2 r0 = ln_relu(a0), r1 = ln_relu(a1), r2 = ln_relu(a2);
    __half2* hb = g_h + (size_t)n * 96;
    hb[lane]      = __float22half2_rn(r0);
    hb[32 + lane] = __float22half2_rn(r1);
    hb[64 + lane] = __float22half2_rn(r2);

    float* ob = out + (size_t)n * OUT_COLS + 64;
    reinterpret_cast<float2*>(ob)[lane] = r0;
    reinterpret_cast<float2*>(ob + 192)[lane] =
        make_float2(r0.x - 0.5f * (r1.x + r2.x), r0.y - 0.5f * (r1.y + r2.y));
}

// ---------- layer 2: gather 3-window h(fp16), 4-neighbor unroll (12 loads in flight) ----------
__global__ __launch_bounds__(256) void layer2_kernel(float* __restrict__ out)
{
    int n    = (blockIdx.x * blockDim.x + threadIdx.x) >> 5;
    int lane = threadIdx.x & 31;
    if (n >= N_NODES) return;

    int beg = g_beg[n], end = beg + g_deg[n];
    float2 a0 = make_float2(0.f, 0.f), a1 = a0, a2 = a0;

    for (int base = beg; base < end; base += 32) {
        int cnt = min(32, end - base);
        int idx = (lane < cnt) ? __ldg(g_csr + base + lane) : 0;
        int j = 0;
        for (; j + 4 <= cnt; j += 4) {
            int s0 = __shfl_sync(0xFFFFFFFFu, idx, j);
            int s1 = __shfl_sync(0xFFFFFFFFu, idx, j + 1);
            int s2 = __shfl_sync(0xFFFFFFFFu, idx, j + 2);
            int s3 = __shfl_sync(0xFFFFFFFFu, idx, j + 3);
            const __half2* hA = g_h + (size_t)s0 * 96;
            const __half2* hB = g_h + (size_t)s1 * 96;
            const __half2* hC = g_h + (size_t)s2 * 96;
            const __half2* hD = g_h + (size_t)s3 * 96;
            float2 A0 = __half22float2(hA[lane]);
            float2 A1 = __half22float2(hA[32 + lane]);
            float2 A2 = __half22float2(hA[64 + lane]);
            float2 B0 = __half22float2(hB[lane]);
            float2 B1 = __half22float2(hB[32 + lane]);
            float2 B2 = __half22float2(hB[64 + lane]);
            float2 C0 = __half22float2(hC[lane]);
            float2 C1 = __half22float2(hC[32 + lane]);
            float2 C2 = __half22float2(hC[64 + lane]);
            float2 D0 = __half22float2(hD[lane]);
            float2 D1 = __half22float2(hD[32 + lane]);
            float2 D2 = __half22float2(hD[64 + lane]);
            acc(a0, A0); acc(a1, A1); acc(a2, A2);
            acc(a0, B0); acc(a1, B1); acc(a2, B2);
            acc(a0, C0); acc(a1, C1); acc(a2, C2);
            acc(a0, D0); acc(a1, D1); acc(a2, D2);
        }
        for (; j < cnt; j++) {
            int s = __shfl_sync(0xFFFFFFFFu, idx, j);
            const __half2* hs = g_h + (size_t)s * 96;
            acc(a0, __half22float2(hs[lane]));
            acc(a1, __half22float2(hs[32 + lane]));
            acc(a2, __half22float2(hs[64 + lane]));
        }
    }

    float2 r0 = ln_relu(a0), r1 = ln_relu(a1), r2 = ln_relu(a2);
    float* ob = out + (size_t)n * OUT_COLS + 128;
    reinterpret_cast<float2*>(ob)[lane] = r0;
    reinterpret_cast<float2*>(ob + 192)[lane] =
        make_float2(r0.x - 0.5f * (r1.x + r2.x), r0.y - 0.5f * (r1.y + r2.y));
}

extern "C" void kernel_launch(void* const* d_in, const int* in_sizes, int n_in,
                              void* d_out, int out_size)
{
    const float* feat = (const float*)d_in[0];
    const int*   age  = (const int*)  d_in[1];
    const int*   src  = (const int*)  d_in[2];
    const int*   dst  = (const int*)  d_in[3];
    float* out = (float*)d_out;

    const int nodeWarpBlocks = (N_NODES * 32 + 255) / 256;  // 12500
    const int nodeBlocks     = (N_NODES + 255) / 256;       // 391
    const int edgeBlocks4    = (N_EDGES + 1023) / 1024;     // 1172

    init_kernel<<<nodeWarpBlocks, 256>>>(feat, age, out);   // also zeros deg/total
    hist_kernel<<<edgeBlocks4, 256>>>(dst);
    alloc_kernel<<<nodeBlocks, 256>>>();
    scatter_kernel<<<edgeBlocks4, 256>>>(src, dst);
    layer1_kernel<<<nodeWarpBlocks, 256>>>(age, out);
    layer2_kernel<<<nodeWarpBlocks, 256>>>(out);
}